// round 14
// baseline (speedup 1.0000x reference)
#include <cuda_runtime.h>
#include <cuda_fp16.h>
#include <mma.h>
using namespace nvcuda;

#define DIM 128
#define MAX_NODES 65536

__device__ __half g_Qh[MAX_NODES * 256];
__device__ __half g_nfh[MAX_NODES * DIM];
__device__ int g_idx64;

typedef wmma::fragment<wmma::matrix_a, 16, 16, 16, __half, wmma::row_major> FragA;
typedef wmma::fragment<wmma::matrix_b, 16, 16, 16, __half, wmma::row_major> FragB;
typedef wmma::fragment<wmma::accumulator, 16, 16, 16, float> FragC;

__device__ __forceinline__ void splitH(float v0, float v1, unsigned& h, unsigned& l) {
    __half2 hh = __floats2half2_rn(v0, v1);
    float2 hf = __half22float2(hh);
    __half2 ll = __floats2half2_rn(v0 - hf.x, v1 - hf.y);
    h = *(unsigned*)&hh;
    l = *(unsigned*)&ll;
}

// ---------------------------------------------------------------------------
// Precompute (unchanged): Q = residual @ [W1b|W1c] fp16-split, Q stored fp16,
// fp16 nf copy stored; block 0 runs the fused dtype detect.
// ---------------------------------------------------------------------------
#define PRE_SMEM (128 * 136 * 2 + 2 * 128 * 136 * 2)

__global__ __launch_bounds__(512, 2)
void precompute_kernel(const float* __restrict__ nf, const float* __restrict__ centroid,
                       const float* __restrict__ W1, const unsigned* __restrict__ eiw,
                       int n_nodes, int npg) {
    extern __shared__ char sm[];
    __half* sW    = (__half*)sm;
    char* sU      = sm + 128 * 136 * 2;
    __half* sA_hi = (__half*)sU;
    __half* sA_lo = sA_hi + 128 * 136;
    float* sStage = (float*)sU;

    const int t = threadIdx.x;
    const int half = blockIdx.x & 1;
    const int base = (blockIdx.x >> 1) * 128;

    if (blockIdx.x == 0) {
        __shared__ int s_any;
        if (t == 0) s_any = 0;
        __syncthreads();
        int found = 0;
        for (int i = t; i < 4096; i += 512)
            if (eiw[2 * i + 1] != 0u) found = 1;
        if (found) atomicOr(&s_any, 1);
        __syncthreads();
        if (t == 0) g_idx64 = (s_any == 0) ? 1 : 0;
    }

    const float* Wsrc = W1 + (1 + half) * DIM * DIM;
    for (int i = t; i < 128 * 128; i += 512) {
        int k = i >> 7, n = i & 127;
        sW[k * 136 + n] = __float2half_rn(Wsrc[i]);
    }
    __syncthreads();

    if (base + 128 > n_nodes) {
        for (int node = base; node < n_nodes; node++) {
            const float* row = nf + (size_t)node * DIM;
            const float* cen = centroid + (size_t)(node / npg) * DIM;
            if (half == 0)
                for (int d = t; d < DIM; d += 512)
                    g_nfh[(size_t)node * DIM + d] = __float2half_rn(row[d]);
            for (int c = t; c < 128; c += 512) {
                const float* wc = Wsrc + c;
                float acc = 0.f;
                for (int k = 0; k < DIM; k++) acc += (row[k] - cen[k]) * wc[k * DIM];
                g_Qh[(size_t)node * 256 + half * 128 + c] = __float2half_rn(acc);
            }
        }
        return;
    }

    for (int i = t; i < 128 * 32; i += 512) {
        int node = i >> 5, c4 = i & 31;
        float4 v = ((const float4*)nf)[(size_t)(base + node) * 32 + c4];
        float4 c = ((const float4*)centroid)[(size_t)((base + node) / npg) * 32 + c4];
        if (half == 0) {
            __half2 n0 = __floats2half2_rn(v.x, v.y);
            __half2 n1 = __floats2half2_rn(v.z, v.w);
            ((uint2*)(g_nfh + (size_t)(base + node) * DIM))[c4] =
                make_uint2(*(unsigned*)&n0, *(unsigned*)&n1);
        }
        unsigned h0, l0, h1, l1;
        splitH(v.x - c.x, v.y - c.y, h0, l0);
        splitH(v.z - c.z, v.w - c.w, h1, l1);
        ((uint2*)(sA_hi + node * 136))[c4] = make_uint2(h0, h1);
        ((uint2*)(sA_lo + node * 136))[c4] = make_uint2(l0, l1);
    }
    __syncthreads();

    const int w = t >> 5;
    const int np = w & 3;
    const int mp = w >> 2;
    {
        const __half* Ah = sA_hi + (mp * 32) * 136;
        const __half* Al = sA_lo + (mp * 32) * 136;

        FragC acc[2][2];
#pragma unroll
        for (int mi = 0; mi < 2; mi++)
#pragma unroll
            for (int n = 0; n < 2; n++) wmma::fill_fragment(acc[mi][n], 0.f);

#pragma unroll
        for (int k = 0; k < 8; k++) {
            FragB b0, b1;
            const __half* bp = sW + (k * 16) * 136 + np * 32;
            wmma::load_matrix_sync(b0, bp, 136);
            wmma::load_matrix_sync(b1, bp + 16, 136);
#pragma unroll
            for (int mi = 0; mi < 2; mi++) {
                FragA a_hi, a_lo;
                wmma::load_matrix_sync(a_hi, Ah + (mi * 16) * 136 + k * 16, 136);
                wmma::load_matrix_sync(a_lo, Al + (mi * 16) * 136 + k * 16, 136);
                wmma::mma_sync(acc[mi][0], a_hi, b0, acc[mi][0]);
                wmma::mma_sync(acc[mi][0], a_lo, b0, acc[mi][0]);
                wmma::mma_sync(acc[mi][1], a_hi, b1, acc[mi][1]);
                wmma::mma_sync(acc[mi][1], a_lo, b1, acc[mi][1]);
            }
        }
        __syncthreads();

#pragma unroll
        for (int mi = 0; mi < 2; mi++)
#pragma unroll
            for (int n = 0; n < 2; n++)
                wmma::store_matrix_sync(
                    sStage + (mp * 32 + mi * 16) * 132 + np * 32 + n * 16,
                    acc[mi][n], 132, wmma::mem_row_major);
    }
    __syncthreads();

    for (int i = t; i < 128 * 64; i += 512) {
        int node = i >> 6, cp = i & 63;
        float v0 = sStage[node * 132 + 2 * cp];
        float v1 = sStage[node * 132 + 2 * cp + 1];
        __half2 hv = __floats2half2_rn(v0, v1);
        *(__half2*)(g_Qh + (size_t)(base + node) * 256 + half * 128 + 2 * cp) = hv;
    }
}

// ---------------------------------------------------------------------------
// Edge kernel: 2 groups x 8 warps, 64-edge tiles, ROTATED software pipeline:
//   top: STS prefetched diffs; bar; [load next idx] MMA; bar; sOut; bar;
//   epilogue with INTERLEAVED next-tile nf prefetch (diffs into 16 regs); bar.
// The ~600cyc gather LDG chain hides under the epilogue phase.
// ---------------------------------------------------------------------------
#define GRP_U (64 * 132 * 4)
#define EDGE_SMEM (128 * 136 * 2 + 2 * GRP_U + 1024)

#define BARG(gid) asm volatile("bar.sync %0, %1;" :: "r"((gid) + 1), "n"(256) : "memory")

__global__ __launch_bounds__(512, 2)
void edge_kernel(const void* __restrict__ ei,
                 const float* __restrict__ W1, const float* __restrict__ b1,
                 const float* __restrict__ W2, const float* __restrict__ b2,
                 float* __restrict__ out, int E) {
    extern __shared__ char sm[];
    __half* sW = (__half*)sm;                        // [128 k][136 n]
    char* sU0 = sm + 128 * 136 * 2;
    float* sB1 = (float*)(sU0 + 2 * GRP_U);          // 128
    float* sW2 = sB1 + 128;                          // 128

    const int t = threadIdx.x;
    for (int i = t; i < DIM * DIM; i += 512) {
        int k = i >> 7, n = i & 127;
        sW[k * 136 + n] = __float2half_rn(W1[i]);
    }
    if (t < DIM) { sB1[t] = b1[t]; sW2[t] = W2[t]; }
    __syncthreads();

    const int w = t >> 5;
    const int lane = t & 31;
    const int g = w >> 3;
    const int w2 = w & 7;
    const int mp = w2 & 1;
    const int np = w2 >> 1;

    char* sUg = sU0 + g * GRP_U;
    __half* sA  = (__half*)sUg;    // [64 e][136 k]
    float* sOut = (float*)sUg;     // [64 e][132 n] (alias)

    const float4 b1v = ((const float4*)sB1)[lane];
    const float4 w2v = ((const float4*)sW2)[lane];
    const float bias2 = b2[0];

    const int mode64 = g_idx64;
    const long long* ei64 = (const long long*)ei;
    const int* ei32 = (const int*)ei;

    const int tiles = (E + 63) >> 6;
    const int pipes = gridDim.x * 2;
    const int tile0 = blockIdx.x * 2 + g;

    // helper lambda-free index load: lanes 0-7 src, 8-15 dst for 8 edges
    uint2 dcur[8];
    int idxv = 0;
    if (tile0 < tiles) {
        int eidL = tile0 * 64 + 8 * w2 + (lane & 7);
        if (lane < 16 && eidL < E) {
            size_t off = (lane < 8) ? (size_t)eidL : (size_t)E + eidL;
            idxv = mode64 ? (int)ei64[off] : ei32[off];
        }
        // prologue gather (blocking)
#pragma unroll
        for (int i = 0; i < 8; i++) {
            int sv = __shfl_sync(0xffffffffu, idxv, i);
            int dv = __shfl_sync(0xffffffffu, idxv, 8 + i);
            uint2 av = ((const uint2*)(g_nfh + (size_t)dv * DIM))[lane];
            uint2 bv = ((const uint2*)(g_nfh + (size_t)sv * DIM))[lane];
            __half2 d0 = __habs2(__hsub2(*(__half2*)&av.x, *(__half2*)&bv.x));
            __half2 d1 = __habs2(__hsub2(*(__half2*)&av.y, *(__half2*)&bv.y));
            dcur[i] = make_uint2(*(unsigned*)&d0, *(unsigned*)&d1);
        }
    }

    for (int tile = tile0; tile < tiles; tile += pipes) {
        const int eb = tile * 64;
        const int nextTile = tile + pipes;
        const bool hasNext = nextTile < tiles;

        // phase 0: commit prefetched diffs to sA
#pragma unroll
        for (int i = 0; i < 8; i++)
            ((uint2*)(sA + (8 * w2 + i) * 136))[lane] = dcur[i];
        BARG(g);

        // next tile's indices (LDG issued here, consumed in epilogue phase)
        int idxn = 0;
        if (hasNext && lane < 16) {
            int eidL = nextTile * 64 + 8 * w2 + (lane & 7);
            if (eidL < E) {
                size_t off = (lane < 8) ? (size_t)eidL : (size_t)E + eidL;
                idxn = mode64 ? (int)ei64[off] : ei32[off];
            }
        }

        // phase 1: MMA
        FragC acc[2][2];
#pragma unroll
        for (int mi = 0; mi < 2; mi++)
#pragma unroll
            for (int n = 0; n < 2; n++) wmma::fill_fragment(acc[mi][n], 0.f);
        {
            const __half* Ah = sA + (mp * 32) * 136;
#pragma unroll
            for (int k = 0; k < 8; k++) {
                FragB b0, b1f;
                const __half* bp = sW + (k * 16) * 136 + np * 32;
                wmma::load_matrix_sync(b0, bp, 136);
                wmma::load_matrix_sync(b1f, bp + 16, 136);
#pragma unroll
                for (int mi = 0; mi < 2; mi++) {
                    FragA af;
                    wmma::load_matrix_sync(af, Ah + (mi * 16) * 136 + k * 16, 136);
                    wmma::mma_sync(acc[mi][0], af, b0, acc[mi][0]);
                    wmma::mma_sync(acc[mi][1], af, b1f, acc[mi][1]);
                }
            }
        }
        BARG(g);   // group done reading A -> safe to alias as sOut

        // phase 2: sOut stores
#pragma unroll
        for (int mi = 0; mi < 2; mi++)
#pragma unroll
            for (int n = 0; n < 2; n++)
                wmma::store_matrix_sync(
                    sOut + (mp * 32 + mi * 16) * 132 + np * 32 + n * 16,
                    acc[mi][n], 132, wmma::mem_row_major);
        BARG(g);   // sOut complete

        // phase 3: epilogue with interleaved next-tile gather prefetch
#pragma unroll
        for (int i = 0; i < 8; i++) {
            // issue next-tile loads for edge i early (hide under Q/epilogue)
            uint2 av, bv;
            if (hasNext) {
                int sv = __shfl_sync(0xffffffffu, idxn, i);
                int dv = __shfl_sync(0xffffffffu, idxn, 8 + i);
                av = ((const uint2*)(g_nfh + (size_t)dv * DIM))[lane];
                bv = ((const uint2*)(g_nfh + (size_t)sv * DIM))[lane];
            }

            int e = 8 * w2 + i;
            int eid = eb + e;
            int sv0 = __shfl_sync(0xffffffffu, idxv, i);
            int dv0 = __shfl_sync(0xffffffffu, idxv, 8 + i);
            float4 o = ((const float4*)(sOut + e * 132))[lane];
            uint2 qdr = ((const uint2*)(g_Qh + (size_t)dv0 * 256))[lane];
            uint2 qsr = ((const uint2*)(g_Qh + (size_t)sv0 * 256 + 128))[lane];
            float2 qd0 = __half22float2(*(__half2*)&qdr.x);
            float2 qd1 = __half22float2(*(__half2*)&qdr.y);
            float2 qs0 = __half22float2(*(__half2*)&qsr.x);
            float2 qs1 = __half22float2(*(__half2*)&qsr.y);
            float s = fmaxf(o.x + qd0.x + qs0.x + b1v.x, 0.f) * w2v.x
                    + fmaxf(o.y + qd0.y + qs0.y + b1v.y, 0.f) * w2v.y
                    + fmaxf(o.z + qd1.x + qs1.x + b1v.z, 0.f) * w2v.z
                    + fmaxf(o.w + qd1.y + qs1.y + b1v.w, 0.f) * w2v.w;
#pragma unroll
            for (int off = 16; off > 0; off >>= 1)
                s += __shfl_down_sync(0xffffffffu, s, off);
            if (lane == 0 && eid < E) out[eid] = s + bias2;

            // convert prefetched loads to diffs (loads have had ~1 epilogue
            // iteration of latency cover)
            if (hasNext) {
                __half2 d0 = __habs2(__hsub2(*(__half2*)&av.x, *(__half2*)&bv.x));
                __half2 d1 = __habs2(__hsub2(*(__half2*)&av.y, *(__half2*)&bv.y));
                dcur[i] = make_uint2(*(unsigned*)&d0, *(unsigned*)&d1);
            }
        }
        idxv = idxn;
        BARG(g);   // sOut reads done -> region reusable as sA next iteration
    }
}

// ---------------------------------------------------------------------------
extern "C" void kernel_launch(void* const* d_in, const int* in_sizes, int n_in,
                              void* d_out, int out_size) {
    const float *nf = 0, *centroid = 0, *W1 = 0, *b1 = 0, *W2 = 0, *b2 = 0;
    const void* ei = 0;
    int nf_elems = 0, cen_elems = 0;
    int last_size1 = -1;

    for (int i = 0; i < n_in; i++) {
        int s = in_sizes[i];
        if (s == 1) { last_size1 = i; continue; }
        if (s == 128) {
            if (!b1) b1 = (const float*)d_in[i];
            else     W2 = (const float*)d_in[i];
            continue;
        }
        if (s == 2048) { centroid = (const float*)d_in[i]; cen_elems = s; continue; }
        if (s == 49152) { W1 = (const float*)d_in[i]; continue; }
        if (s == 2 * out_size) { ei = d_in[i]; continue; }
        if (s > nf_elems) { nf = (const float*)d_in[i]; nf_elems = s; }
    }
    if (last_size1 >= 0) b2 = (const float*)d_in[last_size1];

    const int E = out_size;
    const int n_nodes = nf_elems / DIM;
    const int bs = cen_elems / DIM;
    const int npg = n_nodes / (bs > 0 ? bs : 1);

    cudaFuncSetAttribute(precompute_kernel,
                         cudaFuncAttributeMaxDynamicSharedMemorySize, PRE_SMEM);
    precompute_kernel<<<((n_nodes + 127) / 128) * 2, 512, PRE_SMEM>>>(
        nf, centroid, W1, (const unsigned*)ei, n_nodes, npg);

    int sms = 148;
    cudaDeviceGetAttribute(&sms, cudaDevAttrMultiProcessorCount, 0);

    cudaFuncSetAttribute(edge_kernel,
                         cudaFuncAttributeMaxDynamicSharedMemorySize, EDGE_SMEM);
    edge_kernel<<<sms * 2, 512, EDGE_SMEM>>>(ei, W1, b1, W2, b2, (float*)d_out, E);
}

// round 15
// speedup vs baseline: 1.1244x; 1.1244x over previous
#include <cuda_runtime.h>
#include <cuda_fp16.h>
#include <mma.h>
using namespace nvcuda;

#define DIM 128
#define MAX_NODES 65536

__device__ __half g_Qh[MAX_NODES * 256];
__device__ __half g_nfh[MAX_NODES * DIM];
__device__ int g_idx64;

typedef wmma::fragment<wmma::matrix_a, 16, 16, 16, __half, wmma::row_major> FragA;
typedef wmma::fragment<wmma::matrix_b, 16, 16, 16, __half, wmma::row_major> FragB;
typedef wmma::fragment<wmma::accumulator, 16, 16, 16, float> FragC;

__device__ __forceinline__ void splitH(float v0, float v1, unsigned& h, unsigned& l) {
    __half2 hh = __floats2half2_rn(v0, v1);
    float2 hf = __half22float2(hh);
    __half2 ll = __floats2half2_rn(v0 - hf.x, v1 - hf.y);
    h = *(unsigned*)&hh;
    l = *(unsigned*)&ll;
}

// ---------------------------------------------------------------------------
// Precompute: Q[node][half*128+c] = residual @ W1{b,c} (fp16 A-split, 2-pass),
// stored fp16, with b1 FOLDED into the dst half (half==0). Also stores the
// fp16 nf copy; block 0 runs the fused dtype detect.
// ---------------------------------------------------------------------------
#define PRE_SMEM (128 * 136 * 2 + 2 * 128 * 136 * 2)

__global__ __launch_bounds__(512, 2)
void precompute_kernel(const float* __restrict__ nf, const float* __restrict__ centroid,
                       const float* __restrict__ W1, const float* __restrict__ b1,
                       const unsigned* __restrict__ eiw, int n_nodes, int npg) {
    extern __shared__ char sm[];
    __half* sW    = (__half*)sm;
    char* sU      = sm + 128 * 136 * 2;
    __half* sA_hi = (__half*)sU;
    __half* sA_lo = sA_hi + 128 * 136;
    float* sStage = (float*)sU;

    const int t = threadIdx.x;
    const int half = blockIdx.x & 1;
    const int base = (blockIdx.x >> 1) * 128;

    if (blockIdx.x == 0) {
        __shared__ int s_any;
        if (t == 0) s_any = 0;
        __syncthreads();
        int found = 0;
        for (int i = t; i < 4096; i += 512)
            if (eiw[2 * i + 1] != 0u) found = 1;
        if (found) atomicOr(&s_any, 1);
        __syncthreads();
        if (t == 0) g_idx64 = (s_any == 0) ? 1 : 0;
    }

    const float* Wsrc = W1 + (1 + half) * DIM * DIM;
    for (int i = t; i < 128 * 128; i += 512) {
        int k = i >> 7, n = i & 127;
        sW[k * 136 + n] = __float2half_rn(Wsrc[i]);
    }
    __syncthreads();

    if (base + 128 > n_nodes) {
        for (int node = base; node < n_nodes; node++) {
            const float* row = nf + (size_t)node * DIM;
            const float* cen = centroid + (size_t)(node / npg) * DIM;
            if (half == 0)
                for (int d = t; d < DIM; d += 512)
                    g_nfh[(size_t)node * DIM + d] = __float2half_rn(row[d]);
            for (int c = t; c < 128; c += 512) {
                const float* wc = Wsrc + c;
                float acc = 0.f;
                for (int k = 0; k < DIM; k++) acc += (row[k] - cen[k]) * wc[k * DIM];
                if (half == 0) acc += b1[c];
                g_Qh[(size_t)node * 256 + half * 128 + c] = __float2half_rn(acc);
            }
        }
        return;
    }

    for (int i = t; i < 128 * 32; i += 512) {
        int node = i >> 5, c4 = i & 31;
        float4 v = ((const float4*)nf)[(size_t)(base + node) * 32 + c4];
        float4 c = ((const float4*)centroid)[(size_t)((base + node) / npg) * 32 + c4];
        if (half == 0) {
            __half2 n0 = __floats2half2_rn(v.x, v.y);
            __half2 n1 = __floats2half2_rn(v.z, v.w);
            ((uint2*)(g_nfh + (size_t)(base + node) * DIM))[c4] =
                make_uint2(*(unsigned*)&n0, *(unsigned*)&n1);
        }
        unsigned h0, l0, h1, l1;
        splitH(v.x - c.x, v.y - c.y, h0, l0);
        splitH(v.z - c.z, v.w - c.w, h1, l1);
        ((uint2*)(sA_hi + node * 136))[c4] = make_uint2(h0, h1);
        ((uint2*)(sA_lo + node * 136))[c4] = make_uint2(l0, l1);
    }
    __syncthreads();

    const int w = t >> 5;
    const int np = w & 3;
    const int mp = w >> 2;
    {
        const __half* Ah = sA_hi + (mp * 32) * 136;
        const __half* Al = sA_lo + (mp * 32) * 136;

        FragC acc[2][2];
#pragma unroll
        for (int mi = 0; mi < 2; mi++)
#pragma unroll
            for (int n = 0; n < 2; n++) wmma::fill_fragment(acc[mi][n], 0.f);

#pragma unroll
        for (int k = 0; k < 8; k++) {
            FragB b0, b1f;
            const __half* bp = sW + (k * 16) * 136 + np * 32;
            wmma::load_matrix_sync(b0, bp, 136);
            wmma::load_matrix_sync(b1f, bp + 16, 136);
#pragma unroll
            for (int mi = 0; mi < 2; mi++) {
                FragA a_hi, a_lo;
                wmma::load_matrix_sync(a_hi, Ah + (mi * 16) * 136 + k * 16, 136);
                wmma::load_matrix_sync(a_lo, Al + (mi * 16) * 136 + k * 16, 136);
                wmma::mma_sync(acc[mi][0], a_hi, b0, acc[mi][0]);
                wmma::mma_sync(acc[mi][0], a_lo, b0, acc[mi][0]);
                wmma::mma_sync(acc[mi][1], a_hi, b1f, acc[mi][1]);
                wmma::mma_sync(acc[mi][1], a_lo, b1f, acc[mi][1]);
            }
        }
        __syncthreads();

#pragma unroll
        for (int mi = 0; mi < 2; mi++)
#pragma unroll
            for (int n = 0; n < 2; n++)
                wmma::store_matrix_sync(
                    sStage + (mp * 32 + mi * 16) * 132 + np * 32 + n * 16,
                    acc[mi][n], 132, wmma::mem_row_major);
    }
    __syncthreads();

    // staging -> fp16 Q, with b1 folded into the dst half
    for (int i = t; i < 128 * 64; i += 512) {
        int node = i >> 6, cp = i & 63;
        float v0 = sStage[node * 132 + 2 * cp];
        float v1 = sStage[node * 132 + 2 * cp + 1];
        if (half == 0) { v0 += b1[2 * cp]; v1 += b1[2 * cp + 1]; }
        __half2 hv = __floats2half2_rn(v0, v1);
        *(__half2*)(g_Qh + (size_t)(base + node) * 256 + half * 128 + 2 * cp) = hv;
    }
}

// ---------------------------------------------------------------------------
// Edge kernel (round-12 structure): 512 thr / 16 warps, 128-edge tiles,
// single-pass fp16 A, sOut aliased on A. Epilogue uses a log-fold 8-value
// warp reduction (16 shfl vs 40) and b1 is pre-folded into Q.
// ---------------------------------------------------------------------------
#define EDGE_SMEM (128 * 136 * 2 + 128 * 132 * 4 + 2048)

__global__ __launch_bounds__(512, 2)
void edge_kernel(const void* __restrict__ ei,
                 const float* __restrict__ W1,
                 const float* __restrict__ W2, const float* __restrict__ b2,
                 float* __restrict__ out, int E) {
    extern __shared__ char sm[];
    __half* sW = (__half*)sm;                    // [128 k][136 n]
    char* sU = sm + 128 * 136 * 2;               // union region
    __half* sA = (__half*)sU;                    // [128 e][136 k]
    float* sOut = (float*)sU;                    // [128 e][132 n] (alias)
    float* sW2 = (float*)(sU + 128 * 132 * 4);   // 128
    int* sSrc = (int*)(sW2 + 128);               // 128
    int* sDst = sSrc + 128;                      // 128

    const int t = threadIdx.x;
    for (int i = t; i < DIM * DIM; i += 512) {
        int k = i >> 7, n = i & 127;
        sW[k * 136 + n] = __float2half_rn(W1[i]);   // W1a block [k][n]
    }
    if (t < DIM) sW2[t] = W2[t];
    __syncthreads();

    const int w = t >> 5;
    const int lane = t & 31;
    const int np = w & 3;
    const int mp = w >> 2;

    const float4 w2v = ((const float4*)sW2)[lane];
    const float bias2 = b2[0];

    const int mode64 = g_idx64;
    const long long* ei64 = (const long long*)ei;
    const int* ei32 = (const int*)ei;

    const int tiles = (E + 127) >> 7;
    for (int tile = blockIdx.x; tile < tiles; tile += gridDim.x) {
        const int eb = tile * 128;

        // phase 1: indices
        if (t < 256) {
            int e = t & 127;
            int eid = eb + e;
            int v = 0;
            if (eid < E) {
                if (t < 128) v = mode64 ? (int)ei64[eid] : ei32[eid];
                else         v = mode64 ? (int)ei64[E + eid] : ei32[E + eid];
            }
            if (t < 128) sSrc[e] = v; else sDst[e] = v;
        }
        __syncthreads();

        // phase 2: gather 8 edges/warp from fp16 nf, |diff| in half2
#pragma unroll
        for (int i = 0; i < 8; i++) {
            int e = 8 * w + i;
            int sv = sSrc[e], dv = sDst[e];
            uint2 av = __ldg((const uint2*)(g_nfh + (size_t)dv * DIM) + lane);
            uint2 bv = __ldg((const uint2*)(g_nfh + (size_t)sv * DIM) + lane);
            __half2 d0 = __habs2(__hsub2(*(__half2*)&av.x, *(__half2*)&bv.x));
            __half2 d1 = __habs2(__hsub2(*(__half2*)&av.y, *(__half2*)&bv.y));
            ((uint2*)(sA + e * 136))[lane] =
                make_uint2(*(unsigned*)&d0, *(unsigned*)&d1);
        }
        __syncthreads();

        // phase 3: MMA (single pass), 2m x 2n per warp
        FragC acc[2][2];
#pragma unroll
        for (int mi = 0; mi < 2; mi++)
#pragma unroll
            for (int n = 0; n < 2; n++) wmma::fill_fragment(acc[mi][n], 0.f);
        {
            const __half* Ah = sA + (mp * 32) * 136;
#pragma unroll
            for (int k = 0; k < 8; k++) {
                FragB b0, b1f;
                const __half* bp = sW + (k * 16) * 136 + np * 32;
                wmma::load_matrix_sync(b0, bp, 136);
                wmma::load_matrix_sync(b1f, bp + 16, 136);
#pragma unroll
                for (int mi = 0; mi < 2; mi++) {
                    FragA af;
                    wmma::load_matrix_sync(af, Ah + (mi * 16) * 136 + k * 16, 136);
                    wmma::mma_sync(acc[mi][0], af, b0, acc[mi][0]);
                    wmma::mma_sync(acc[mi][1], af, b1f, acc[mi][1]);
                }
            }
        }
        __syncthreads();   // done reading A -> alias as sOut

#pragma unroll
        for (int mi = 0; mi < 2; mi++)
#pragma unroll
            for (int n = 0; n < 2; n++)
                wmma::store_matrix_sync(
                    sOut + (mp * 32 + mi * 16) * 132 + np * 32 + n * 16,
                    acc[mi][n], 132, wmma::mem_row_major);
        __syncthreads();

        // phase 4: epilogue — per-lane partials for 8 edges, then log-fold
        float s[8];
#pragma unroll
        for (int i = 0; i < 8; i++) {
            int e = 8 * w + i;
            int sv = sSrc[e], dv = sDst[e];
            float4 o = ((const float4*)(sOut + e * 132))[lane];
            uint2 qdr = __ldg((const uint2*)(g_Qh + (size_t)dv * 256) + lane);
            uint2 qsr = __ldg((const uint2*)(g_Qh + (size_t)sv * 256 + 128) + lane);
            float2 qd0 = __half22float2(*(__half2*)&qdr.x);
            float2 qd1 = __half22float2(*(__half2*)&qdr.y);
            float2 qs0 = __half22float2(*(__half2*)&qsr.x);
            float2 qs1 = __half22float2(*(__half2*)&qsr.y);
            s[i] = fmaxf(o.x + qd0.x + qs0.x, 0.f) * w2v.x
                 + fmaxf(o.y + qd0.y + qs0.y, 0.f) * w2v.y
                 + fmaxf(o.z + qd1.x + qs1.x, 0.f) * w2v.z
                 + fmaxf(o.w + qd1.y + qs1.y, 0.f) * w2v.w;
        }

        // log-fold reduction: 8 sums with 16 shuffles
#pragma unroll
        for (int i = 0; i < 8; i++)
            s[i] += __shfl_xor_sync(0xffffffffu, s[i], 16);
        float u[4];
#pragma unroll
        for (int j = 0; j < 4; j++) {
            u[j] = (lane & 16) ? s[j + 4] : s[j];
            u[j] += __shfl_xor_sync(0xffffffffu, u[j], 8);
        }
        float v2[2];
#pragma unroll
        for (int m = 0; m < 2; m++) {
            v2[m] = (lane & 8) ? u[m + 2] : u[m];
            v2[m] += __shfl_xor_sync(0xffffffffu, v2[m], 4);
        }
        float x = (lane & 4) ? v2[1] : v2[0];
        x += __shfl_xor_sync(0xffffffffu, x, 2);
        x += __shfl_xor_sync(0xffffffffu, x, 1);
        if ((lane & 3) == 0) {
            int eloc = ((lane >> 2) & 1) + 2 * ((lane >> 3) & 1) + 4 * ((lane >> 4) & 1);
            int eid = eb + 8 * w + eloc;
            if (eid < E) out[eid] = x + bias2;
        }
        __syncthreads();   // sOut (== A region) free for next gather
    }
}

// ---------------------------------------------------------------------------
extern "C" void kernel_launch(void* const* d_in, const int* in_sizes, int n_in,
                              void* d_out, int out_size) {
    const float *nf = 0, *centroid = 0, *W1 = 0, *b1 = 0, *W2 = 0, *b2 = 0;
    const void* ei = 0;
    int nf_elems = 0, cen_elems = 0;
    int last_size1 = -1;

    for (int i = 0; i < n_in; i++) {
        int s = in_sizes[i];
        if (s == 1) { last_size1 = i; continue; }
        if (s == 128) {
            if (!b1) b1 = (const float*)d_in[i];
            else     W2 = (const float*)d_in[i];
            continue;
        }
        if (s == 2048) { centroid = (const float*)d_in[i]; cen_elems = s; continue; }
        if (s == 49152) { W1 = (const float*)d_in[i]; continue; }
        if (s == 2 * out_size) { ei = d_in[i]; continue; }
        if (s > nf_elems) { nf = (const float*)d_in[i]; nf_elems = s; }
    }
    if (last_size1 >= 0) b2 = (const float*)d_in[last_size1];

    const int E = out_size;
    const int n_nodes = nf_elems / DIM;
    const int bs = cen_elems / DIM;
    const int npg = n_nodes / (bs > 0 ? bs : 1);

    cudaFuncSetAttribute(precompute_kernel,
                         cudaFuncAttributeMaxDynamicSharedMemorySize, PRE_SMEM);
    precompute_kernel<<<((n_nodes + 127) / 128) * 2, 512, PRE_SMEM>>>(
        nf, centroid, W1, b1, (const unsigned*)ei, n_nodes, npg);

    int sms = 148;
    cudaDeviceGetAttribute(&sms, cudaDevAttrMultiProcessorCount, 0);

    cudaFuncSetAttribute(edge_kernel,
                         cudaFuncAttributeMaxDynamicSharedMemorySize, EDGE_SMEM);
    edge_kernel<<<sms * 2, 512, EDGE_SMEM>>>(ei, W1, W2, b2, (float*)d_out, E);
}